// round 9
// baseline (speedup 1.0000x reference)
#include <cuda_runtime.h>
#include <cuda_bf16.h>
#include <math.h>

// Problem constants
#define B_   16
#define T_   8192
#define V_   256
#define CE_  256
#define CR_  128
#define CS_  256
#define GC_  64
#define L_   12

// Tiling
#define TT   104
#define WP   128
#define XS   132
#define SKS  106
#define NT   512
#define O1S  56

// smem layout (floats)
#define OFF_BUFA 0
#define N_BUFA   (128*XS)
#define OFF_GBUF (OFF_BUFA + N_BUFA)
#define N_GBUF   (64*XS)
#define OFF_SKIP (OFF_GBUF + N_GBUF)
#define N_SKIP   (CS_*SKS)
#define OFF_WST  (OFF_SKIP + N_SKIP)
#define N_WST    4224                 // init-conv staging only
#define OFF_TOK  (OFF_WST + N_WST)
#define SMEM_BYTES ((OFF_TOK)*4 + 132*4)

typedef unsigned long long u64;

__device__ __forceinline__ u64 pk2(float lo, float hi) {
    u64 r; asm("mov.b64 %0, {%1,%2};" : "=l"(r) : "f"(lo), "f"(hi)); return r;
}
__device__ __forceinline__ u64 bc2(float x) { return pk2(x, x); }
__device__ __forceinline__ void fma2(u64& d, u64 a, u64 b) {
    asm("fma.rn.f32x2 %0, %1, %2, %0;" : "+l"(d) : "l"(a), "l"(b));
}
__device__ __forceinline__ u64 add2(u64 a, u64 b) {
    u64 r; asm("add.rn.f32x2 %0, %1, %2;" : "=l"(r) : "l"(a), "l"(b)); return r;
}
__device__ __forceinline__ float2 up2(u64 a) {
    float2 f; asm("mov.b64 {%0,%1}, %2;" : "=f"(f.x), "=f"(f.y) : "l"(a)); return f;
}
__device__ __forceinline__ float sigmoidf_(float x) {
    return __fdividef(1.0f, 1.0f + __expf(-x));
}
__device__ __forceinline__ float tanhf_(float x) {
    return 1.0f - __fdividef(2.0f, __expf(2.0f * x) + 1.0f);
}

__global__ void __launch_bounds__(NT, 1) wavenet_fused(
    const int*   __restrict__ tokens,
    const float* __restrict__ emb,
    const float* __restrict__ w_init, const float* __restrict__ b_init,
    const float* __restrict__ w_dil,  const float* __restrict__ b_dil,
    const float* __restrict__ w_res,  const float* __restrict__ b_res,
    const float* __restrict__ w_skip, const float* __restrict__ b_skip,
    const float* __restrict__ w_out1, const float* __restrict__ b_out1,
    const float* __restrict__ w_out2, const float* __restrict__ b_out2,
    float* __restrict__ out)
{
    extern __shared__ float sm[];
    float* bufA  = sm + OFF_BUFA;   // x activations [128][XS]
    float* gbuf  = sm + OFF_GBUF;   // gate output [64][XS] (init: h staging)
    float* skipS = sm + OFF_SKIP;   // skip accum [256][SKS]
    float* wst   = sm + OFF_WST;    // init-conv weight staging
    int*   tokb  = (int*)(sm + OFF_TOK);

    const int tid  = threadIdx.x;
    const int tile = blockIdx.x;
    const int bb   = blockIdx.y;
    const int t0   = tile * TT;
    const int pzero = (tile == 0) ? 24 : 0;

    for (int q = tid; q < WP + 1; q += NT) {
        int t = t0 - 25 + q;
        tokb[q] = (t >= 0 && t < T_) ? tokens[bb * T_ + t] : -1;
    }
    for (int i = tid; i < N_SKIP; i += NT) skipS[i] = 0.0f;

    // conv/residual mapping (R4 proven): 4 channels x 4 pairs per thread
    const int cg = tid >> 4;      // 0..31
    const int pg = tid & 15;      // 0..15
    const int c0 = 2 * cg;        // channels {c0, c0+1, c0+64, c0+65}
    const int q0 = 2 * pg;        // pairs at q0 + 32k, k=0..3

    // ======================= init conv (emb -> x0), staged (runs once) ==========
    {
        u64 acc[4][4];
        #pragma unroll
        for (int ic = 0; ic < 4; ++ic)
            #pragma unroll
            for (int k = 0; k < 4; ++k) acc[ic][k] = 0ULL;

        __syncthreads();
        for (int ch = 0; ch < 16; ++ch) {       // ce chunks of 16
            const int ceb = ch * 16;
            for (int idx = tid; idx < (WP + 1) * 4; idx += NT) {
                int q = idx >> 2; int ce4 = (idx & 3) << 2;
                int tok = tokb[q];
                float4 v = make_float4(0.f, 0.f, 0.f, 0.f);
                if (tok >= 0) v = *reinterpret_cast<const float4*>(emb + tok * CE_ + ceb + ce4);
                gbuf[(ce4 + 0) * XS + q] = v.x;
                gbuf[(ce4 + 1) * XS + q] = v.y;
                gbuf[(ce4 + 2) * XS + q] = v.z;
                gbuf[(ce4 + 3) * XS + q] = v.w;
            }
            for (int idx = tid; idx < 2048; idx += NT) {
                int ce = idx & 15; int co = idx >> 4;
                float2 w2 = *reinterpret_cast<const float2*>(w_init + ((co * CE_ + ceb + ce) << 1));
                wst[ce * 260 + co]       = w2.x;
                wst[ce * 260 + 128 + co] = w2.y;
            }
            __syncthreads();
            #pragma unroll
            for (int ce = 0; ce < 16; ++ce) {
                const float* hr = gbuf + ce * XS;
                const float* wr = wst + ce * 260;
                u64 w00 = bc2(wr[c0]),        w10 = bc2(wr[128 + c0]);
                u64 w01 = bc2(wr[c0 + 1]),    w11 = bc2(wr[128 + c0 + 1]);
                u64 w02 = bc2(wr[c0 + 64]),   w12 = bc2(wr[128 + c0 + 64]);
                u64 w03 = bc2(wr[c0 + 65]),   w13 = bc2(wr[128 + c0 + 65]);
                #pragma unroll
                for (int k = 0; k < 4; ++k) {
                    int q = q0 + 32 * k;
                    u64 A = *reinterpret_cast<const u64*>(hr + q);
                    float s = hr[q + 2];
                    float2 av = up2(A);
                    u64 T1 = pk2(av.y, s);
                    fma2(acc[0][k], w00, A); fma2(acc[0][k], w10, T1);
                    fma2(acc[1][k], w01, A); fma2(acc[1][k], w11, T1);
                    fma2(acc[2][k], w02, A); fma2(acc[2][k], w12, T1);
                    fma2(acc[3][k], w03, A); fma2(acc[3][k], w13, T1);
                }
            }
            __syncthreads();
        }
        #pragma unroll
        for (int ic = 0; ic < 4; ++ic) {
            int co = (ic < 2) ? (c0 + ic) : (c0 + 62 + ic);
            u64 bp = bc2(__ldg(b_init + co));
            #pragma unroll
            for (int k = 0; k < 4; ++k) {
                int q = q0 + 32 * k;
                u64 v = (q < pzero) ? 0ULL : add2(acc[ic][k], bp);
                *reinterpret_cast<u64*>(bufA + co * XS + q) = v;
            }
        }
    }
    __syncthreads();

    // skip mapping: 4 cs channels x (7|6) pairs
    const int csg = tid >> 3;                 // 0..63
    const int cs0 = 4 * csg;
    const int jgS = tid & 7;                  // 0..7
    const int spS = (jgS < 4) ? 7 * jgS : 28 + 6 * (jgS - 4);
    const int npS = (jgS < 4) ? 7 : 6;

    // ============================ layers (2 syncs each) ============================
    for (int l = 0; l < L_; ++l) {
        // ---- dilated conv (k=2, d=2): weights direct from L2, depth-1 prefetch ----
        u64 acc2[4][4];
        #pragma unroll
        for (int ic = 0; ic < 4; ++ic)
            #pragma unroll
            for (int k = 0; k < 4; ++k) acc2[ic][k] = 0ULL;

        const float* wd = w_dil + (size_t)l * CR_ * CR_ * 2;
        const float* pA = wd + (c0       * CR_) * 2;   // row of co=c0   : [ci][k] pairs
        const float* pB = wd + ((c0 + 1) * CR_) * 2;
        const float* pC = wd + ((c0 + 64) * CR_) * 2;
        const float* pD = wd + ((c0 + 65) * CR_) * 2;

        float4 nA = *reinterpret_cast<const float4*>(pA);   // taps for ci=0,1
        float4 nB = *reinterpret_cast<const float4*>(pB);
        float4 nC = *reinterpret_cast<const float4*>(pC);
        float4 nD = *reinterpret_cast<const float4*>(pD);

        #pragma unroll 2
        for (int ci2 = 0; ci2 < 64; ++ci2) {            // pairs (2*ci2, 2*ci2+1)
            float4 wA = nA, wB = nB, wC = nC, wD = nD;
            int nx = (ci2 < 63) ? (ci2 * 4 + 4) : (ci2 * 4);
            nA = *reinterpret_cast<const float4*>(pA + nx);
            nB = *reinterpret_cast<const float4*>(pB + nx);
            nC = *reinterpret_cast<const float4*>(pC + nx);
            nD = *reinterpret_cast<const float4*>(pD + nx);

            // ---- ci = 2*ci2 ----
            {
                const int ci = 2 * ci2;
                const float* xr = bufA + ci * XS;
                u64 xm[4], xp[4];
                xm[0] = (q0 >= 2) ? *reinterpret_cast<const u64*>(xr + q0 - 2) : 0ULL;
                xp[0] = *reinterpret_cast<const u64*>(xr + q0);
                #pragma unroll
                for (int k = 1; k < 4; ++k) {
                    xm[k] = *reinterpret_cast<const u64*>(xr + q0 + 32 * k - 2);
                    xp[k] = *reinterpret_cast<const u64*>(xr + q0 + 32 * k);
                }
                u64 b0 = bc2(wA.x), b1 = bc2(wA.y), b2 = bc2(wB.x), b3 = bc2(wB.y);
                u64 b4 = bc2(wC.x), b5 = bc2(wC.y), b6 = bc2(wD.x), b7 = bc2(wD.y);
                #pragma unroll
                for (int k = 0; k < 4; ++k) {
                    fma2(acc2[0][k], b0, xm[k]); fma2(acc2[0][k], b1, xp[k]);
                    fma2(acc2[1][k], b2, xm[k]); fma2(acc2[1][k], b3, xp[k]);
                    fma2(acc2[2][k], b4, xm[k]); fma2(acc2[2][k], b5, xp[k]);
                    fma2(acc2[3][k], b6, xm[k]); fma2(acc2[3][k], b7, xp[k]);
                }
            }
            // ---- ci = 2*ci2 + 1 ----
            {
                const int ci = 2 * ci2 + 1;
                const float* xr = bufA + ci * XS;
                u64 xm[4], xp[4];
                xm[0] = (q0 >= 2) ? *reinterpret_cast<const u64*>(xr + q0 - 2) : 0ULL;
                xp[0] = *reinterpret_cast<const u64*>(xr + q0);
                #pragma unroll
                for (int k = 1; k < 4; ++k) {
                    xm[k] = *reinterpret_cast<const u64*>(xr + q0 + 32 * k - 2);
                    xp[k] = *reinterpret_cast<const u64*>(xr + q0 + 32 * k);
                }
                u64 b0 = bc2(wA.z), b1 = bc2(wA.w), b2 = bc2(wB.z), b3 = bc2(wB.w);
                u64 b4 = bc2(wC.z), b5 = bc2(wC.w), b6 = bc2(wD.z), b7 = bc2(wD.w);
                #pragma unroll
                for (int k = 0; k < 4; ++k) {
                    fma2(acc2[0][k], b0, xm[k]); fma2(acc2[0][k], b1, xp[k]);
                    fma2(acc2[1][k], b2, xm[k]); fma2(acc2[1][k], b3, xp[k]);
                    fma2(acc2[2][k], b4, xm[k]); fma2(acc2[2][k], b5, xp[k]);
                    fma2(acc2[3][k], b6, xm[k]); fma2(acc2[3][k], b7, xp[k]);
                }
            }
        }

        // ---- gate (writes gbuf; prior readers of gbuf synced at layer end) ----
        {
            const float* bd = b_dil + l * CR_;
            float gb0 = __ldg(bd + c0), gb1 = __ldg(bd + c0 + 1);
            float gb2 = __ldg(bd + c0 + 64), gb3 = __ldg(bd + c0 + 65);
            #pragma unroll
            for (int k = 0; k < 4; ++k) {
                int q = q0 + 32 * k;
                float2 a0 = up2(acc2[0][k]);
                float2 a1 = up2(acc2[1][k]);
                float2 a2v = up2(acc2[2][k]);
                float2 a3v = up2(acc2[3][k]);
                float g0a = tanhf_(a0.x + gb0) * sigmoidf_(a2v.x + gb2);
                float g0b = tanhf_(a0.y + gb0) * sigmoidf_(a2v.y + gb2);
                float g1a = tanhf_(a1.x + gb1) * sigmoidf_(a3v.x + gb3);
                float g1b = tanhf_(a1.y + gb1) * sigmoidf_(a3v.y + gb3);
                *reinterpret_cast<u64*>(gbuf + c0 * XS + q)       = pk2(g0a, g0b);
                *reinterpret_cast<u64*>(gbuf + (c0 + 1) * XS + q) = pk2(g1a, g1b);
            }
        }
        __syncthreads();   // gate writes visible to skip/res

        // ---- skip: 4 cs x (7|6) pairs, weights direct (row float4 per 4 gc) ----
        {
            const float* wsk = w_skip + (size_t)l * CS_ * GC_;
            u64 sacc[4][7];
            #pragma unroll
            for (int i = 0; i < 4; ++i)
                #pragma unroll
                for (int kk = 0; kk < 7; ++kk) sacc[i][kk] = 0ULL;
            for (int gb = 0; gb < 16; ++gb) {
                float4 w0 = *reinterpret_cast<const float4*>(wsk + (cs0 + 0) * GC_ + 4 * gb);
                float4 w1 = *reinterpret_cast<const float4*>(wsk + (cs0 + 1) * GC_ + 4 * gb);
                float4 w2 = *reinterpret_cast<const float4*>(wsk + (cs0 + 2) * GC_ + 4 * gb);
                float4 w3 = *reinterpret_cast<const float4*>(wsk + (cs0 + 3) * GC_ + 4 * gb);
                const float* wf0 = &w0.x; const float* wf1 = &w1.x;
                const float* wf2 = &w2.x; const float* wf3 = &w3.x;
                #pragma unroll
                for (int j = 0; j < 4; ++j) {
                    int gc = 4 * gb + j;
                    u64 wb0 = bc2(wf0[j]), wb1 = bc2(wf1[j]);
                    u64 wb2 = bc2(wf2[j]), wb3 = bc2(wf3[j]);
                    const u64* gr = reinterpret_cast<const u64*>(gbuf + gc * XS + 24 + 2 * spS);
                    #pragma unroll
                    for (int kk = 0; kk < 7; ++kk) {
                        u64 gv = gr[kk];
                        fma2(sacc[0][kk], wb0, gv);
                        fma2(sacc[1][kk], wb1, gv);
                        fma2(sacc[2][kk], wb2, gv);
                        fma2(sacc[3][kk], wb3, gv);
                    }
                }
            }
            const float* bsk = b_skip + l * CS_;
            #pragma unroll
            for (int i = 0; i < 4; ++i) {
                u64 bbp = bc2(__ldg(bsk + cs0 + i));
                u64* sp = reinterpret_cast<u64*>(skipS + (cs0 + i) * SKS + 2 * spS);
                #pragma unroll
                for (int kk = 0; kk < 7; ++kk)
                    if (kk < npS) sp[kk] = add2(sp[kk], add2(sacc[i][kk], bbp));
            }
        }

        // ---- residual: x += W_res g (+b), weights direct ----
        {
            const float* wrp = w_res + (size_t)l * CR_ * GC_;
            u64 racc[4][4];
            #pragma unroll
            for (int ic = 0; ic < 4; ++ic)
                #pragma unroll
                for (int k = 0; k < 4; ++k) racc[ic][k] = 0ULL;
            for (int gb = 0; gb < 16; ++gb) {
                float4 wL0 = *reinterpret_cast<const float4*>(wrp + (c0)      * GC_ + 4 * gb);
                float4 wL1 = *reinterpret_cast<const float4*>(wrp + (c0 + 1)  * GC_ + 4 * gb);
                float4 wH0 = *reinterpret_cast<const float4*>(wrp + (c0 + 64) * GC_ + 4 * gb);
                float4 wH1 = *reinterpret_cast<const float4*>(wrp + (c0 + 65) * GC_ + 4 * gb);
                const float* fL0 = &wL0.x; const float* fL1 = &wL1.x;
                const float* fH0 = &wH0.x; const float* fH1 = &wH1.x;
                #pragma unroll
                for (int j = 0; j < 4; ++j) {
                    int gc = 4 * gb + j;
                    const float* grow = gbuf + gc * XS;
                    u64 g0 = *reinterpret_cast<const u64*>(grow + q0);
                    u64 g1 = *reinterpret_cast<const u64*>(grow + q0 + 32);
                    u64 g2 = *reinterpret_cast<const u64*>(grow + q0 + 64);
                    u64 g3 = *reinterpret_cast<const u64*>(grow + q0 + 96);
                    u64 w0 = bc2(fL0[j]), w1 = bc2(fL1[j]);
                    u64 w2 = bc2(fH0[j]), w3 = bc2(fH1[j]);
                    fma2(racc[0][0], w0, g0); fma2(racc[0][1], w0, g1);
                    fma2(racc[0][2], w0, g2); fma2(racc[0][3], w0, g3);
                    fma2(racc[1][0], w1, g0); fma2(racc[1][1], w1, g1);
                    fma2(racc[1][2], w1, g2); fma2(racc[1][3], w1, g3);
                    fma2(racc[2][0], w2, g0); fma2(racc[2][1], w2, g1);
                    fma2(racc[2][2], w2, g2); fma2(racc[2][3], w2, g3);
                    fma2(racc[3][0], w3, g0); fma2(racc[3][1], w3, g1);
                    fma2(racc[3][2], w3, g2); fma2(racc[3][3], w3, g3);
                }
            }
            const float* br = b_res + l * CR_;
            #pragma unroll
            for (int ic = 0; ic < 4; ++ic) {
                int co = (ic < 2) ? (c0 + ic) : (c0 + 62 + ic);
                u64 bp = bc2(__ldg(br + co));
                #pragma unroll
                for (int k = 0; k < 4; ++k) {
                    int q = q0 + 32 * k;
                    u64* xp_ = reinterpret_cast<u64*>(bufA + co * XS + q);
                    u64 v = add2(*xp_, add2(racc[ic][k], bp));
                    if (q < pzero) v = 0ULL;
                    *xp_ = v;
                }
            }
        }
        __syncthreads();   // end of layer
    }

    // ======================= output head =======================
    for (int i = tid; i < N_SKIP; i += NT) {
        float v = skipS[i] * (1.0f / 12.0f);
        skipS[i] = v > 0.0f ? v : 0.0f;
    }
    __syncthreads();

    float* o1buf = bufA;
    const int c0h = tid >> 1;
    const int jh  = 26 * (tid & 1);

    for (int half = 0; half < 2; ++half) {
        const int jbase = half * 52;
        // ---- out1: weights direct ----
        u64 a2p[13];
        #pragma unroll
        for (int kk = 0; kk < 13; ++kk) a2p[kk] = 0ULL;
        for (int kb4 = 0; kb4 < 64; ++kb4) {
            float4 wv = *reinterpret_cast<const float4*>(w_out1 + c0h * CS_ + 4 * kb4);
            const float* wf = &wv.x;
            #pragma unroll
            for (int j = 0; j < 4; ++j) {
                int k = 4 * kb4 + j;
                u64 wb = bc2(wf[j]);
                const u64* sr = reinterpret_cast<const u64*>(skipS + k * SKS + jbase + jh);
                #pragma unroll
                for (int kk = 0; kk < 13; ++kk) fma2(a2p[kk], wb, sr[kk]);
            }
        }
        {
            float bi = __ldg(b_out1 + c0h);
            float* op = o1buf + c0h * O1S + jh;
            #pragma unroll
            for (int kk = 0; kk < 13; ++kk) {
                float2 v = up2(a2p[kk]);
                float v0 = v.x + bi; v0 = v0 > 0.0f ? v0 : 0.0f;
                float v1 = v.y + bi; v1 = v1 > 0.0f ? v1 : 0.0f;
                *reinterpret_cast<u64*>(op + 2 * kk) = pk2(v0, v1);
            }
        }
        __syncthreads();
        // ---- out2: weights direct ----
        u64 a3p[13];
        #pragma unroll
        for (int kk = 0; kk < 13; ++kk) a3p[kk] = 0ULL;
        for (int kb4 = 0; kb4 < 64; ++kb4) {
            float4 wv = *reinterpret_cast<const float4*>(w_out2 + c0h * CS_ + 4 * kb4);
            const float* wf = &wv.x;
            #pragma unroll
            for (int j = 0; j < 4; ++j) {
                int k = 4 * kb4 + j;
                u64 wb = bc2(wf[j]);
                const u64* orr = reinterpret_cast<const u64*>(o1buf + k * O1S + jh);
                #pragma unroll
                for (int kk = 0; kk < 13; ++kk) fma2(a3p[kk], wb, orr[kk]);
            }
        }
        {
            float bo = __ldg(b_out2 + c0h);
            float* orow = out + ((size_t)bb * V_ + c0h) * T_;
            #pragma unroll
            for (int kk = 0; kk < 13; ++kk) {
                int t = t0 + jbase + jh + 2 * kk;
                float2 v = up2(a3p[kk]);
                v.x += bo; v.y += bo;
                if (t + 1 < T_) {
                    *reinterpret_cast<float2*>(orow + t) = v;
                } else if (t < T_) {
                    orow[t] = v.x;
                }
            }
        }
        __syncthreads();   // o1buf reuse / next half
    }
}

extern "C" void kernel_launch(void* const* d_in, const int* in_sizes, int n_in,
                              void* d_out, int out_size) {
    const int*   tokens = (const int*)  d_in[0];
    const float* emb    = (const float*)d_in[1];
    const float* w_init = (const float*)d_in[2];
    const float* b_init = (const float*)d_in[3];
    const float* w_dil  = (const float*)d_in[4];
    const float* b_dil  = (const float*)d_in[5];
    const float* w_res  = (const float*)d_in[6];
    const float* b_res  = (const float*)d_in[7];
    const float* w_skip = (const float*)d_in[8];
    const float* b_skip = (const float*)d_in[9];
    const float* w_out1 = (const float*)d_in[10];
    const float* b_out1 = (const float*)d_in[11];
    const float* w_out2 = (const float*)d_in[12];
    const float* b_out2 = (const float*)d_in[13];
    float* out = (float*)d_out;

    cudaFuncSetAttribute(wavenet_fused, cudaFuncAttributeMaxDynamicSharedMemorySize, SMEM_BYTES);
    dim3 grid((T_ + TT - 1) / TT, B_);
    wavenet_fused<<<grid, NT, SMEM_BYTES>>>(
        tokens, emb, w_init, b_init, w_dil, b_dil, w_res, b_res,
        w_skip, b_skip, w_out1, b_out1, w_out2, b_out2, out);
}

// round 10
// speedup vs baseline: 1.0436x; 1.0436x over previous
#include <cuda_runtime.h>
#include <cuda_bf16.h>
#include <math.h>

// Problem constants
#define B_   16
#define T_   8192
#define V_   256
#define CE_  256
#define CR_  128
#define CS_  256
#define GC_  64
#define L_   12

// Tiling
#define TT   104
#define WP   128
#define XS   132
#define SKS  106
#define NT   512
#define O1S  56

// smem layout (floats)
#define OFF_BUFA 0
#define N_BUFA   (128*XS)
#define OFF_GBUF (OFF_BUFA + N_BUFA)
#define N_GBUF   (64*XS)              // 8448; conv-weight staging overlay (32*260=8320)
#define OFF_SKIP (OFF_GBUF + N_GBUF)
#define N_SKIP   (CS_*SKS)
#define OFF_WST  (OFF_SKIP + N_SKIP)
#define N_WST    4224
#define OFF_TOK  (OFF_WST + N_WST)
#define SMEM_BYTES ((OFF_TOK)*4 + 132*4)

typedef unsigned long long u64;

__device__ __forceinline__ u64 pk2(float lo, float hi) {
    u64 r; asm("mov.b64 %0, {%1,%2};" : "=l"(r) : "f"(lo), "f"(hi)); return r;
}
__device__ __forceinline__ u64 bc2(float x) { return pk2(x, x); }
__device__ __forceinline__ void fma2(u64& d, u64 a, u64 b) {
    asm("fma.rn.f32x2 %0, %1, %2, %0;" : "+l"(d) : "l"(a), "l"(b));
}
__device__ __forceinline__ u64 add2(u64 a, u64 b) {
    u64 r; asm("add.rn.f32x2 %0, %1, %2;" : "=l"(r) : "l"(a), "l"(b)); return r;
}
__device__ __forceinline__ float2 up2(u64 a) {
    float2 f; asm("mov.b64 {%0,%1}, %2;" : "=f"(f.x), "=f"(f.y) : "l"(a)); return f;
}
__device__ __forceinline__ float sigmoidf_(float x) {
    return __fdividef(1.0f, 1.0f + __expf(-x));
}

__global__ void __launch_bounds__(NT, 1) wavenet_fused(
    const int*   __restrict__ tokens,
    const float* __restrict__ emb,
    const float* __restrict__ w_init, const float* __restrict__ b_init,
    const float* __restrict__ w_dil,  const float* __restrict__ b_dil,
    const float* __restrict__ w_res,  const float* __restrict__ b_res,
    const float* __restrict__ w_skip, const float* __restrict__ b_skip,
    const float* __restrict__ w_out1, const float* __restrict__ b_out1,
    const float* __restrict__ w_out2, const float* __restrict__ b_out2,
    float* __restrict__ out)
{
    extern __shared__ float sm[];
    float* bufA  = sm + OFF_BUFA;   // x activations [128][XS]
    float* gbuf  = sm + OFF_GBUF;   // gate output [64][XS]; conv-weight staging overlay
    float* skipS = sm + OFF_SKIP;   // skip accum [256][SKS]
    float* wst   = sm + OFF_WST;    // small weight staging
    int*   tokb  = (int*)(sm + OFF_TOK);

    const int tid  = threadIdx.x;
    const int tile = blockIdx.x;
    const int bb   = blockIdx.y;
    const int t0   = tile * TT;
    const int pzero = (tile == 0) ? 24 : 0;

    for (int q = tid; q < WP + 1; q += NT) {
        int t = t0 - 25 + q;
        tokb[q] = (t >= 0 && t < T_) ? tokens[bb * T_ + t] : -1;
    }
    for (int i = tid; i < N_SKIP; i += NT) skipS[i] = 0.0f;

    // conv/residual mapping: 4 channels; ADJACENT-PAIR position blocks
    const int cg = tid >> 4;      // 0..31
    const int pg = tid & 15;      // 0..15
    const int c0 = 2 * cg;        // channels {c0, c0+1, c0+64, c0+65}
    const int q0 = 2 * pg;        // init-conv mapping (strided pairs, proven)
    const int p0 = 4 * pg;        // layer mapping: blocks [p0,p0+4) and [p0+64,p0+68)

    // ======================= init conv (emb -> x0), proven layout ===============
    {
        u64 acc[4][4];
        #pragma unroll
        for (int ic = 0; ic < 4; ++ic)
            #pragma unroll
            for (int k = 0; k < 4; ++k) acc[ic][k] = 0ULL;

        __syncthreads();
        for (int ch = 0; ch < 16; ++ch) {       // ce chunks of 16
            const int ceb = ch * 16;
            for (int idx = tid; idx < (WP + 1) * 4; idx += NT) {
                int q = idx >> 2; int ce4 = (idx & 3) << 2;
                int tok = tokb[q];
                float4 v = make_float4(0.f, 0.f, 0.f, 0.f);
                if (tok >= 0) v = *reinterpret_cast<const float4*>(emb + tok * CE_ + ceb + ce4);
                gbuf[(ce4 + 0) * XS + q] = v.x;
                gbuf[(ce4 + 1) * XS + q] = v.y;
                gbuf[(ce4 + 2) * XS + q] = v.z;
                gbuf[(ce4 + 3) * XS + q] = v.w;
            }
            for (int idx = tid; idx < 2048; idx += NT) {
                int ce = idx & 15; int co = idx >> 4;
                float2 w2 = *reinterpret_cast<const float2*>(w_init + ((co * CE_ + ceb + ce) << 1));
                wst[ce * 260 + co]       = w2.x;
                wst[ce * 260 + 128 + co] = w2.y;
            }
            __syncthreads();
            #pragma unroll
            for (int ce = 0; ce < 16; ++ce) {
                const float* hr = gbuf + ce * XS;
                const float* wr = wst + ce * 260;
                u64 w00 = bc2(wr[c0]),        w10 = bc2(wr[128 + c0]);
                u64 w01 = bc2(wr[c0 + 1]),    w11 = bc2(wr[128 + c0 + 1]);
                u64 w02 = bc2(wr[c0 + 64]),   w12 = bc2(wr[128 + c0 + 64]);
                u64 w03 = bc2(wr[c0 + 65]),   w13 = bc2(wr[128 + c0 + 65]);
                #pragma unroll
                for (int k = 0; k < 4; ++k) {
                    int q = q0 + 32 * k;
                    u64 A = *reinterpret_cast<const u64*>(hr + q);
                    float s = hr[q + 2];
                    float2 av = up2(A);
                    u64 T1 = pk2(av.y, s);
                    fma2(acc[0][k], w00, A); fma2(acc[0][k], w10, T1);
                    fma2(acc[1][k], w01, A); fma2(acc[1][k], w11, T1);
                    fma2(acc[2][k], w02, A); fma2(acc[2][k], w12, T1);
                    fma2(acc[3][k], w03, A); fma2(acc[3][k], w13, T1);
                }
            }
            __syncthreads();
        }
        #pragma unroll
        for (int ic = 0; ic < 4; ++ic) {
            int co = (ic < 2) ? (c0 + ic) : (c0 + 62 + ic);
            u64 bp = bc2(__ldg(b_init + co));
            #pragma unroll
            for (int k = 0; k < 4; ++k) {
                int q = q0 + 32 * k;
                u64 v = (q < pzero) ? 0ULL : add2(acc[ic][k], bp);
                *reinterpret_cast<u64*>(bufA + co * XS + q) = v;
            }
        }
    }
    __syncthreads();

    // skip mapping (proven): 2 cs channels x 13 pairs
    const int cs0 = 2 * (tid >> 2);
    const int j0  = 26 * (tid & 3);

    float* wstD = gbuf;   // dilated conv weight staging overlays gbuf

    // ============================ layers ============================
    for (int l = 0; l < L_; ++l) {
        // ---- dilated conv (k=2, d=2): adjacent-pair blocks ----
        // acc2[ic][k]: ic in {c0,c0+1,c0+64,c0+65}; k: pairs (p0,p0+1),(p0+2,p0+3),
        //              (p0+64,p0+65),(p0+66,p0+67)
        u64 acc2[4][4];
        #pragma unroll
        for (int ic = 0; ic < 4; ++ic)
            #pragma unroll
            for (int k = 0; k < 4; ++k) acc2[ic][k] = 0ULL;

        const float* wd = w_dil + (size_t)l * CR_ * CR_ * 2;
        for (int ch = 0; ch < 4; ++ch) {        // ci chunks of 32
            const int cib = ch * 32;
            __syncthreads();   // gbuf free (prev consumers done)
            for (int idx = tid; idx < 4096; idx += NT) {
                int ci = idx & 31; int co = idx >> 5;
                float2 w2 = *reinterpret_cast<const float2*>(wd + ((co * CR_ + cib + ci) << 1));
                *reinterpret_cast<u64*>(wstD + ci * 260 + 2 * co) = pk2(w2.x, w2.y);
            }
            __syncthreads();
            #pragma unroll
            for (int ci = 0; ci < 32; ++ci) {
                const float* xr = bufA + (cib + ci) * XS;
                ulonglong2 F = *reinterpret_cast<const ulonglong2*>(xr + p0);       // pairs (p0,p0+1),(p0+2,p0+3)
                ulonglong2 G = *reinterpret_cast<const ulonglong2*>(xr + p0 + 64);  // (p0+64,..),(p0+66,..)
                u64 xm  = (p0 >= 4) ? *reinterpret_cast<const u64*>(xr + p0 - 2) : 0ULL;
                u64 xm2 = *reinterpret_cast<const u64*>(xr + p0 + 62);
                const float* wr = wstD + ci * 260 + 2 * c0;
                float4 wlo = *reinterpret_cast<const float4*>(wr);
                float4 whi = *reinterpret_cast<const float4*>(wr + 128);
                u64 b0 = bc2(wlo.x), b1 = bc2(wlo.y), b2 = bc2(wlo.z), b3 = bc2(wlo.w);
                u64 b4 = bc2(whi.x), b5 = bc2(whi.y), b6 = bc2(whi.z), b7 = bc2(whi.w);
                // k=0: tap0 = xm,  tap1 = F.x ; k=1: tap0 = F.x, tap1 = F.y
                fma2(acc2[0][0], b0, xm);  fma2(acc2[0][0], b1, F.x);
                fma2(acc2[0][1], b0, F.x); fma2(acc2[0][1], b1, F.y);
                fma2(acc2[1][0], b2, xm);  fma2(acc2[1][0], b3, F.x);
                fma2(acc2[1][1], b2, F.x); fma2(acc2[1][1], b3, F.y);
                fma2(acc2[2][0], b4, xm);  fma2(acc2[2][0], b5, F.x);
                fma2(acc2[2][1], b4, F.x); fma2(acc2[2][1], b5, F.y);
                fma2(acc2[3][0], b6, xm);  fma2(acc2[3][0], b7, F.x);
                fma2(acc2[3][1], b6, F.x); fma2(acc2[3][1], b7, F.y);
                // k=2: tap0 = xm2, tap1 = G.x ; k=3: tap0 = G.x, tap1 = G.y
                fma2(acc2[0][2], b0, xm2); fma2(acc2[0][2], b1, G.x);
                fma2(acc2[0][3], b0, G.x); fma2(acc2[0][3], b1, G.y);
                fma2(acc2[1][2], b2, xm2); fma2(acc2[1][2], b3, G.x);
                fma2(acc2[1][3], b2, G.x); fma2(acc2[1][3], b3, G.y);
                fma2(acc2[2][2], b4, xm2); fma2(acc2[2][2], b5, G.x);
                fma2(acc2[2][3], b4, G.x); fma2(acc2[2][3], b5, G.y);
                fma2(acc2[3][2], b6, xm2); fma2(acc2[3][2], b7, G.x);
                fma2(acc2[3][3], b6, G.x); fma2(acc2[3][3], b7, G.y);
            }
        }
        __syncthreads();   // conv reads of wstD(gbuf) done before gate writes gbuf
        // ---- gate: vectorized STS.128 ----
        {
            const float* bd = b_dil + l * CR_;
            #pragma unroll
            for (int i = 0; i < 2; ++i) {
                float bL = __ldg(bd + c0 + i);
                float bH = __ldg(bd + c0 + 64 + i);
                // block 0: positions p0..p0+3 (acc k=0,1; ic=i lower / ic=2+i upper)
                {
                    float2 a0 = up2(acc2[i][0]),     h0 = up2(acc2[2 + i][0]);
                    float2 a1 = up2(acc2[i][1]),     h1 = up2(acc2[2 + i][1]);
                    float g0 = tanhf(a0.x + bL) * sigmoidf_(h0.x + bH);
                    float g1 = tanhf(a0.y + bL) * sigmoidf_(h0.y + bH);
                    float g2 = tanhf(a1.x + bL) * sigmoidf_(h1.x + bH);
                    float g3 = tanhf(a1.y + bL) * sigmoidf_(h1.y + bH);
                    ulonglong2 s; s.x = pk2(g0, g1); s.y = pk2(g2, g3);
                    *reinterpret_cast<ulonglong2*>(gbuf + (c0 + i) * XS + p0) = s;
                }
                // block 1: positions p0+64..p0+67 (acc k=2,3)
                {
                    float2 a0 = up2(acc2[i][2]),     h0 = up2(acc2[2 + i][2]);
                    float2 a1 = up2(acc2[i][3]),     h1 = up2(acc2[2 + i][3]);
                    float g0 = tanhf(a0.x + bL) * sigmoidf_(h0.x + bH);
                    float g1 = tanhf(a0.y + bL) * sigmoidf_(h0.y + bH);
                    float g2 = tanhf(a1.x + bL) * sigmoidf_(h1.x + bH);
                    float g3 = tanhf(a1.y + bL) * sigmoidf_(h1.y + bH);
                    ulonglong2 s; s.x = pk2(g0, g1); s.y = pk2(g2, g3);
                    *reinterpret_cast<ulonglong2*>(gbuf + (c0 + i) * XS + p0 + 64) = s;
                }
            }
        }
        __syncthreads();

        // ---- skip accumulation (proven layout, unchanged) ----
        {
            const float* wsk = w_skip + (size_t)l * CS_ * GC_;
            u64 sacc0[13], sacc1[13];
            #pragma unroll
            for (int kk = 0; kk < 13; ++kk) { sacc0[kk] = 0ULL; sacc1[kk] = 0ULL; }
            for (int gch = 0; gch < 4; ++gch) {
                const int gcb = gch * 16;
                for (int idx = tid; idx < 4096; idx += NT) {
                    int gc = idx & 15; int cs = idx >> 4;
                    wst[gc * 260 + cs] = wsk[cs * GC_ + gcb + gc];
                }
                __syncthreads();
                #pragma unroll
                for (int gc = 0; gc < 16; ++gc) {
                    const float* wrow = wst + gc * 260;
                    u64 wb0 = bc2(wrow[cs0]);
                    u64 wb1 = bc2(wrow[cs0 + 1]);
                    const u64* gr = reinterpret_cast<const u64*>(gbuf + (gcb + gc) * XS + 24 + j0);
                    #pragma unroll
                    for (int kk = 0; kk < 13; ++kk) {
                        u64 gv = gr[kk];
                        fma2(sacc0[kk], wb0, gv);
                        fma2(sacc1[kk], wb1, gv);
                    }
                }
                __syncthreads();
            }
            const float* bsk = b_skip + l * CS_;
            u64 bbp0 = bc2(__ldg(bsk + cs0));
            u64 bbp1 = bc2(__ldg(bsk + cs0 + 1));
            u64* sp0 = reinterpret_cast<u64*>(skipS + cs0 * SKS + j0);
            u64* sp1 = reinterpret_cast<u64*>(skipS + (cs0 + 1) * SKS + j0);
            #pragma unroll
            for (int kk = 0; kk < 13; ++kk) {
                sp0[kk] = add2(sp0[kk], add2(sacc0[kk], bbp0));
                sp1[kk] = add2(sp1[kk], add2(sacc1[kk], bbp1));
            }
        }

        // ---- residual: x = x + W_res g (+b), vectorized acts ----
        {
            const float* wrp = w_res + (size_t)l * CR_ * GC_;
            u64 racc[4][4];
            #pragma unroll
            for (int ic = 0; ic < 4; ++ic)
                #pragma unroll
                for (int k = 0; k < 4; ++k) racc[ic][k] = 0ULL;
            for (int gch = 0; gch < 2; ++gch) {
                const int gcb = gch * 32;
                __syncthreads();
                for (int idx = tid; idx < 4096; idx += NT) {
                    int gc = idx & 31; int co = idx >> 5;
                    wst[gc * 130 + co] = wrp[co * GC_ + gcb + gc];
                }
                __syncthreads();
                #pragma unroll
                for (int gc = 0; gc < 32; ++gc) {
                    const float* grow = gbuf + (gcb + gc) * XS;
                    ulonglong2 gA = *reinterpret_cast<const ulonglong2*>(grow + p0);
                    ulonglong2 gB = *reinterpret_cast<const ulonglong2*>(grow + p0 + 64);
                    const float* wrow = wst + gc * 130;
                    float2 wlo = *reinterpret_cast<const float2*>(wrow + c0);
                    float2 whi = *reinterpret_cast<const float2*>(wrow + c0 + 64);
                    u64 w0 = bc2(wlo.x), w1 = bc2(wlo.y), w2 = bc2(whi.x), w3 = bc2(whi.y);
                    fma2(racc[0][0], w0, gA.x); fma2(racc[0][1], w0, gA.y);
                    fma2(racc[0][2], w0, gB.x); fma2(racc[0][3], w0, gB.y);
                    fma2(racc[1][0], w1, gA.x); fma2(racc[1][1], w1, gA.y);
                    fma2(racc[1][2], w1, gB.x); fma2(racc[1][3], w1, gB.y);
                    fma2(racc[2][0], w2, gA.x); fma2(racc[2][1], w2, gA.y);
                    fma2(racc[2][2], w2, gB.x); fma2(racc[2][3], w2, gB.y);
                    fma2(racc[3][0], w3, gA.x); fma2(racc[3][1], w3, gA.y);
                    fma2(racc[3][2], w3, gB.x); fma2(racc[3][3], w3, gB.y);
                }
            }
            __syncthreads();
            const float* br = b_res + l * CR_;
            #pragma unroll
            for (int ic = 0; ic < 4; ++ic) {
                int co = (ic < 2) ? (c0 + ic) : (c0 + 62 + ic);
                u64 bp = bc2(__ldg(br + co));
                ulonglong2* X0 = reinterpret_cast<ulonglong2*>(bufA + co * XS + p0);
                ulonglong2 v0 = *X0;
                v0.x = add2(v0.x, add2(racc[ic][0], bp));
                v0.y = add2(v0.y, add2(racc[ic][1], bp));
                if (p0 < pzero) { v0.x = 0ULL; v0.y = 0ULL; }
                *X0 = v0;
                ulonglong2* X1 = reinterpret_cast<ulonglong2*>(bufA + co * XS + p0 + 64);
                ulonglong2 v1 = *X1;
                v1.x = add2(v1.x, add2(racc[ic][2], bp));
                v1.y = add2(v1.y, add2(racc[ic][3], bp));
                *X1 = v1;
            }
        }
        __syncthreads();
    }

    // ======================= output head (proven layout) =======================
    for (int i = tid; i < N_SKIP; i += NT) {
        float v = skipS[i] * (1.0f / 12.0f);
        skipS[i] = v > 0.0f ? v : 0.0f;
    }

    float* o1buf = bufA;
    const int c0h = tid >> 1;
    const int jh  = 26 * (tid & 1);

    for (int half = 0; half < 2; ++half) {
        const int jbase = half * 52;
        // ---- out1 ----
        u64 a2p[13];
        #pragma unroll
        for (int kk = 0; kk < 13; ++kk) a2p[kk] = 0ULL;
        for (int kch = 0; kch < 16; ++kch) {
            const int kb = kch * 16;
            __syncthreads();
            for (int idx = tid; idx < 4096; idx += NT) {
                int k = idx & 15; int c = idx >> 4;
                wst[k * 260 + c] = w_out1[c * CS_ + kb + k];
            }
            __syncthreads();
            #pragma unroll 4
            for (int k = 0; k < 16; ++k) {
                u64 wb = bc2(wst[k * 260 + c0h]);
                const u64* sr = reinterpret_cast<const u64*>(skipS + (kb + k) * SKS + jbase + jh);
                #pragma unroll
                for (int kk = 0; kk < 13; ++kk) fma2(a2p[kk], wb, sr[kk]);
            }
        }
        __syncthreads();
        {
            float bi = __ldg(b_out1 + c0h);
            float* op = o1buf + c0h * O1S + jh;
            #pragma unroll
            for (int kk = 0; kk < 13; ++kk) {
                float2 v = up2(a2p[kk]);
                float v0 = v.x + bi; v0 = v0 > 0.0f ? v0 : 0.0f;
                float v1 = v.y + bi; v1 = v1 > 0.0f ? v1 : 0.0f;
                *reinterpret_cast<u64*>(op + 2 * kk) = pk2(v0, v1);
            }
        }
        __syncthreads();
        // ---- out2 ----
        u64 a3p[13];
        #pragma unroll
        for (int kk = 0; kk < 13; ++kk) a3p[kk] = 0ULL;
        for (int kch = 0; kch < 16; ++kch) {
            const int kb = kch * 16;
            __syncthreads();
            for (int idx = tid; idx < 4096; idx += NT) {
                int k = idx & 15; int c = idx >> 4;
                wst[k * 260 + c] = w_out2[c * CS_ + kb + k];
            }
            __syncthreads();
            #pragma unroll 4
            for (int k = 0; k < 16; ++k) {
                u64 wb = bc2(wst[k * 260 + c0h]);
                const u64* orr = reinterpret_cast<const u64*>(o1buf + (kb + k) * O1S + jh);
                #pragma unroll
                for (int kk = 0; kk < 13; ++kk) fma2(a3p[kk], wb, orr[kk]);
            }
        }
        {
            float bo = __ldg(b_out2 + c0h);
            float* orow = out + ((size_t)bb * V_ + c0h) * T_;
            #pragma unroll
            for (int kk = 0; kk < 13; ++kk) {
                int t = t0 + jbase + jh + 2 * kk;
                float2 v = up2(a3p[kk]);
                v.x += bo; v.y += bo;
                if (t + 1 < T_) {
                    *reinterpret_cast<float2*>(orow + t) = v;
                } else if (t < T_) {
                    orow[t] = v.x;
                }
            }
        }
        __syncthreads();
    }
}

extern "C" void kernel_launch(void* const* d_in, const int* in_sizes, int n_in,
                              void* d_out, int out_size) {
    const int*   tokens = (const int*)  d_in[0];
    const float* emb    = (const float*)d_in[1];
    const float* w_init = (const float*)d_in[2];
    const float* b_init = (const float*)d_in[3];
    const float* w_dil  = (const float*)d_in[4];
    const float* b_dil  = (const float*)d_in[5];
    const float* w_res  = (const float*)d_in[6];
    const float* b_res  = (const float*)d_in[7];
    const float* w_skip = (const float*)d_in[8];
    const float* b_skip = (const float*)d_in[9];
    const float* w_out1 = (const float*)d_in[10];
    const float* b_out1 = (const float*)d_in[11];
    const float* w_out2 = (const float*)d_in[12];
    const float* b_out2 = (const float*)d_in[13];
    float* out = (float*)d_out;

    cudaFuncSetAttribute(wavenet_fused, cudaFuncAttributeMaxDynamicSharedMemorySize, SMEM_BYTES);
    dim3 grid((T_ + TT - 1) / TT, B_);
    wavenet_fused<<<grid, NT, SMEM_BYTES>>>(
        tokens, emb, w_init, b_init, w_dil, b_dil, w_res, b_res,
        w_skip, b_skip, w_out1, b_out1, w_out2, b_out2, out);
}